// round 1
// baseline (speedup 1.0000x reference)
#include <cuda_runtime.h>
#include <cstdint>

#define NUM_USERS 50000
#define NUM_ITEMS 50000
#define NUM_NODES (NUM_USERS + NUM_ITEMS)   // 100000
#define EMB_DIM 128
#define NUM_EDGES 2000000
#define TOTAL_ELEMS (NUM_NODES * EMB_DIM)   // 12,800,000 floats
#define TOTAL_VEC4 (TOTAL_ELEMS / 4)        // 3,200,000 float4

// Scratch ping-pong buffers (device globals: no allocation allowed).
__device__ float g_bufA[TOTAL_ELEMS];
__device__ float g_bufB[TOTAL_ELEMS];

// ---------------------------------------------------------------------------
// init: bufA = emb ; out = emb (accumulator) ; bufB = 0 (first scatter target)
// ---------------------------------------------------------------------------
__global__ void lgcn_init(const float* __restrict__ emb, float* __restrict__ out) {
    int i = blockIdx.x * blockDim.x + threadIdx.x;
    if (i < TOTAL_VEC4) {
        float4 v = ((const float4*)emb)[i];
        ((float4*)g_bufA)[i] = v;
        ((float4*)out)[i]    = v;
        ((float4*)g_bufB)[i] = make_float4(0.f, 0.f, 0.f, 0.f);
    }
}

// ---------------------------------------------------------------------------
// SpMM scatter: y[rows[e]] += vals[e] * x[cols[e]]
// One warp per edge; lane handles float4 (32 lanes x 4 = 128 = EMB_DIM).
// Vectorized no-return atomic (red.global.add.v4.f32, sm_90+).
// ---------------------------------------------------------------------------
__global__ void lgcn_spmm(const float* __restrict__ x, float* __restrict__ y,
                          const int* __restrict__ rows, const int* __restrict__ cols,
                          const float* __restrict__ vals) {
    int gtid = blockIdx.x * blockDim.x + threadIdx.x;
    int e    = gtid >> 5;
    int lane = gtid & 31;
    if (e >= NUM_EDGES) return;

    int   r = __ldg(rows + e);
    int   c = __ldg(cols + e);
    float v = __ldg(vals + e);

    const float4* xs = (const float4*)(x + (size_t)c * EMB_DIM);
    float4 xv = __ldg(xs + lane);

    float4 p;
    p.x = xv.x * v; p.y = xv.y * v; p.z = xv.z * v; p.w = xv.w * v;

    float* dst = y + (size_t)r * EMB_DIM + lane * 4;
    asm volatile("red.global.add.v4.f32 [%0], {%1, %2, %3, %4};"
                 :: "l"(dst), "f"(p.x), "f"(p.y), "f"(p.z), "f"(p.w)
                 : "memory");
}

// ---------------------------------------------------------------------------
// accumulate layer result into out and zero the buffer that will be the NEXT
// scatter target (fused — avoids a separate memset pass over 51 MB).
// ---------------------------------------------------------------------------
__global__ void lgcn_add_zero(float* __restrict__ out, const float* __restrict__ src,
                              float* __restrict__ zbuf) {
    int i = blockIdx.x * blockDim.x + threadIdx.x;
    if (i < TOTAL_VEC4) {
        float4 o = ((const float4*)out)[i];
        float4 s = ((const float4*)src)[i];
        o.x += s.x; o.y += s.y; o.z += s.z; o.w += s.w;
        ((float4*)out)[i]  = o;
        ((float4*)zbuf)[i] = make_float4(0.f, 0.f, 0.f, 0.f);
    }
}

// Final layer: out = (out + src) * 0.25
__global__ void lgcn_final(float* __restrict__ out, const float* __restrict__ src) {
    int i = blockIdx.x * blockDim.x + threadIdx.x;
    if (i < TOTAL_VEC4) {
        float4 o = ((const float4*)out)[i];
        float4 s = ((const float4*)src)[i];
        o.x = (o.x + s.x) * 0.25f;
        o.y = (o.y + s.y) * 0.25f;
        o.z = (o.z + s.z) * 0.25f;
        o.w = (o.w + s.w) * 0.25f;
        ((float4*)out)[i] = o;
    }
}

extern "C" void kernel_launch(void* const* d_in, const int* in_sizes, int n_in,
                              void* d_out, int out_size) {
    const float* emb  = (const float*)d_in[0];
    const int*   rows = (const int*)  d_in[1];
    const int*   cols = (const int*)  d_in[2];
    const float* vals = (const float*)d_in[3];
    float*       out  = (float*)d_out;

    float* bufA = nullptr;
    float* bufB = nullptr;
    cudaGetSymbolAddress((void**)&bufA, g_bufA);
    cudaGetSymbolAddress((void**)&bufB, g_bufB);

    const int TB = 256;
    const int elem_blocks = (TOTAL_VEC4 + TB - 1) / TB;
    const long long spmm_threads = (long long)NUM_EDGES * 32;
    const int spmm_blocks = (int)((spmm_threads + TB - 1) / TB);

    // init: A = emb, out = emb, B = 0
    lgcn_init<<<elem_blocks, TB>>>(emb, out);

    // layer 1: B += spmm(A); out += B; zero A
    lgcn_spmm<<<spmm_blocks, TB>>>(bufA, bufB, rows, cols, vals);
    lgcn_add_zero<<<elem_blocks, TB>>>(out, bufB, bufA);

    // layer 2: A += spmm(B); out += A; zero B
    lgcn_spmm<<<spmm_blocks, TB>>>(bufB, bufA, rows, cols, vals);
    lgcn_add_zero<<<elem_blocks, TB>>>(out, bufA, bufB);

    // layer 3: B += spmm(A); out = (out + B) / 4
    lgcn_spmm<<<spmm_blocks, TB>>>(bufA, bufB, rows, cols, vals);
    lgcn_final<<<elem_blocks, TB>>>(out, bufB);
}

// round 2
// speedup vs baseline: 2.6639x; 2.6639x over previous
#include <cuda_runtime.h>
#include <cstdint>

#define NUM_USERS 50000
#define NUM_ITEMS 50000
#define NUM_NODES (NUM_USERS + NUM_ITEMS)   // 100000
#define EMB_DIM 128
#define NUM_EDGES 2000000
#define TOTAL_ELEMS (NUM_NODES * EMB_DIM)   // 12,800,000 floats
#define TOTAL_VEC4 (TOTAL_ELEMS / 4)        // 3,200,000 float4

#define SCAN_T 512
#define SCAN_NB ((NUM_NODES + SCAN_T - 1) / SCAN_T)   // 196

// ---- device scratch (no allocation allowed) ----
__device__ int   g_cnt[NUM_NODES];
__device__ int   g_rowptr[NUM_NODES + 1];
__device__ int   g_cursor[NUM_NODES];       // also used as scan temp
__device__ int   g_blocksums[SCAN_NB];
__device__ int2  g_csr[NUM_EDGES];          // {col, val-as-int}
__device__ float g_bufA[TOTAL_ELEMS];
__device__ float g_bufB[TOTAL_ELEMS];

// ---------------------------------------------------------------------------
// CSR build
// ---------------------------------------------------------------------------
__global__ void k_zero_cnt() {
    int i = blockIdx.x * blockDim.x + threadIdx.x;
    if (i < NUM_NODES) g_cnt[i] = 0;
}

__global__ void k_hist(const int* __restrict__ rows) {
    int e = blockIdx.x * blockDim.x + threadIdx.x;
    if (e < NUM_EDGES) atomicAdd(&g_cnt[rows[e]], 1);
}

// per-block inclusive scan of g_cnt; within-block inclusive -> g_cursor (temp),
// block total -> g_blocksums[b]
__global__ void k_scan1() {
    __shared__ int sh[SCAN_T];
    int t = threadIdx.x;
    int i = blockIdx.x * SCAN_T + t;
    int v = (i < NUM_NODES) ? g_cnt[i] : 0;
    sh[t] = v;
    __syncthreads();
    #pragma unroll
    for (int off = 1; off < SCAN_T; off <<= 1) {
        int tmp = (t >= off) ? sh[t - off] : 0;
        __syncthreads();
        sh[t] += tmp;
        __syncthreads();
    }
    if (i < NUM_NODES) g_cursor[i] = sh[t];
    if (t == SCAN_T - 1) g_blocksums[blockIdx.x] = sh[t];
}

// exclusive scan of block sums (single block)
__global__ void k_scan2() {
    __shared__ int sh[256];
    int t = threadIdx.x;   // blockDim = 256 >= SCAN_NB
    int v = (t < SCAN_NB) ? g_blocksums[t] : 0;
    sh[t] = v;
    __syncthreads();
    #pragma unroll
    for (int off = 1; off < 256; off <<= 1) {
        int tmp = (t >= off) ? sh[t - off] : 0;
        __syncthreads();
        sh[t] += tmp;
        __syncthreads();
    }
    if (t < SCAN_NB) g_blocksums[t] = sh[t] - v;   // exclusive
}

// combine: global inclusive -> rowptr[i+1]; cursor[i] = exclusive = incl - cnt
__global__ void k_scan3() {
    int i = blockIdx.x * blockDim.x + threadIdx.x;
    if (i < NUM_NODES) {
        int gi = g_cursor[i] + g_blocksums[i / SCAN_T];
        g_rowptr[i + 1] = gi;
        g_cursor[i] = gi - g_cnt[i];
        if (i == 0) g_rowptr[0] = 0;
    }
}

__global__ void k_scatter(const int* __restrict__ rows, const int* __restrict__ cols,
                          const float* __restrict__ vals) {
    int e = blockIdx.x * blockDim.x + threadIdx.x;
    if (e < NUM_EDGES) {
        int r = rows[e];
        int p = atomicAdd(&g_cursor[r], 1);
        g_csr[p] = make_int2(cols[e], __float_as_int(vals[e]));
    }
}

// ---------------------------------------------------------------------------
// CSR SpMM: one warp per row, float4 per lane, register accumulation,
// single full-row store (no atomics, no pre-zeroed target needed).
// ---------------------------------------------------------------------------
__global__ void k_spmm(const float* __restrict__ x, float* __restrict__ y) {
    int w    = (blockIdx.x * blockDim.x + threadIdx.x) >> 5;
    int lane = threadIdx.x & 31;
    if (w >= NUM_NODES) return;

    int s = __ldg(&g_rowptr[w]);
    int e = __ldg(&g_rowptr[w + 1]);

    float4 acc = make_float4(0.f, 0.f, 0.f, 0.f);
    const float4* xs = (const float4*)x;

    int i = s;
    for (; i + 1 < e; i += 2) {
        int2 e0 = __ldg(&g_csr[i]);
        int2 e1 = __ldg(&g_csr[i + 1]);
        float v0 = __int_as_float(e0.y);
        float v1 = __int_as_float(e1.y);
        float4 x0 = __ldg(xs + (size_t)e0.x * 32 + lane);
        float4 x1 = __ldg(xs + (size_t)e1.x * 32 + lane);
        acc.x += v0 * x0.x + v1 * x1.x;
        acc.y += v0 * x0.y + v1 * x1.y;
        acc.z += v0 * x0.z + v1 * x1.z;
        acc.w += v0 * x0.w + v1 * x1.w;
    }
    if (i < e) {
        int2 e0 = __ldg(&g_csr[i]);
        float v0 = __int_as_float(e0.y);
        float4 x0 = __ldg(xs + (size_t)e0.x * 32 + lane);
        acc.x += v0 * x0.x;
        acc.y += v0 * x0.y;
        acc.z += v0 * x0.z;
        acc.w += v0 * x0.w;
    }
    ((float4*)y)[(size_t)w * 32 + lane] = acc;
}

// ---------------------------------------------------------------------------
// final: out = 0.25 * (emb + l1 + l2 + l3), l3 already in out
// ---------------------------------------------------------------------------
__global__ void k_final(const float* __restrict__ emb, float* __restrict__ out) {
    int i = blockIdx.x * blockDim.x + threadIdx.x;
    if (i < TOTAL_VEC4) {
        float4 o = ((const float4*)out)[i];
        float4 m = ((const float4*)emb)[i];
        float4 a = ((const float4*)g_bufA)[i];
        float4 b = ((const float4*)g_bufB)[i];
        o.x = 0.25f * (o.x + m.x + a.x + b.x);
        o.y = 0.25f * (o.y + m.y + a.y + b.y);
        o.z = 0.25f * (o.z + m.z + a.z + b.z);
        o.w = 0.25f * (o.w + m.w + a.w + b.w);
        ((float4*)out)[i] = o;
    }
}

extern "C" void kernel_launch(void* const* d_in, const int* in_sizes, int n_in,
                              void* d_out, int out_size) {
    const float* emb  = (const float*)d_in[0];
    const int*   rows = (const int*)  d_in[1];
    const int*   cols = (const int*)  d_in[2];
    const float* vals = (const float*)d_in[3];
    float*       out  = (float*)d_out;

    float* bufA = nullptr;
    float* bufB = nullptr;
    cudaGetSymbolAddress((void**)&bufA, g_bufA);
    cudaGetSymbolAddress((void**)&bufB, g_bufB);

    const int TB = 256;
    const int node_blocks = (NUM_NODES + TB - 1) / TB;
    const int edge_blocks = (NUM_EDGES + TB - 1) / TB;
    const int elem_blocks = (TOTAL_VEC4 + TB - 1) / TB;
    const int spmm_blocks = (NUM_NODES * 32 + TB - 1) / TB;

    // ---- build CSR ----
    k_zero_cnt<<<node_blocks, TB>>>();
    k_hist<<<edge_blocks, TB>>>(rows);
    k_scan1<<<SCAN_NB, SCAN_T>>>();
    k_scan2<<<1, 256>>>();
    k_scan3<<<node_blocks, TB>>>();
    k_scatter<<<edge_blocks, TB>>>(rows, cols, vals);

    // ---- 3 propagation layers (gather-mode, no atomics) ----
    k_spmm<<<spmm_blocks, TB>>>(emb,  bufA);   // l1
    k_spmm<<<spmm_blocks, TB>>>(bufA, bufB);   // l2
    k_spmm<<<spmm_blocks, TB>>>(bufB, out);    // l3 -> straight into d_out

    // ---- out = (emb + l1 + l2 + l3) / 4 ----
    k_final<<<elem_blocks, TB>>>(emb, out);
}

// round 3
// speedup vs baseline: 3.9455x; 1.4811x over previous
#include <cuda_runtime.h>
#include <cuda_fp16.h>
#include <cstdint>

#define NUM_USERS 50000
#define NUM_ITEMS 50000
#define NUM_NODES (NUM_USERS + NUM_ITEMS)   // 100000
#define EMB_DIM 128
#define NUM_EDGES 2000000
#define TOTAL_ELEMS (NUM_NODES * EMB_DIM)   // 12,800,000 floats
#define TOTAL_VEC4 (TOTAL_ELEMS / 4)        // 3,200,000 float4 / uint2-half4

#define SCAN_T 512
#define SCAN_NB ((NUM_NODES + SCAN_T - 1) / SCAN_T)   // 196

// ---- device scratch (no allocation allowed) ----
__device__ int   g_cnt[NUM_NODES];
__device__ int   g_rowptr[NUM_NODES + 1];
__device__ int   g_cursor[NUM_NODES];
__device__ int   g_blocksums[SCAN_NB];
__device__ int2  g_csr[NUM_EDGES];              // {col, val-as-int(f32)}
// fp16 feature buffers: 128 halves per node = 32 uint2 per node
__device__ uint2 g_h0[TOTAL_VEC4];
__device__ uint2 g_h1[TOTAL_VEC4];
__device__ uint2 g_h2[TOTAL_VEC4];

// ---------------------------------------------------------------------------
// convert emb -> fp16 (h0), and zero the per-row counters (fused)
// ---------------------------------------------------------------------------
__global__ void k_convert_zero(const float* __restrict__ emb) {
    int i = blockIdx.x * blockDim.x + threadIdx.x;
    if (i < TOTAL_VEC4) {
        float4 v = ((const float4*)emb)[i];
        __half2 lo = __floats2half2_rn(v.x, v.y);
        __half2 hi = __floats2half2_rn(v.z, v.w);
        uint2 packed;
        packed.x = *(unsigned int*)&lo;
        packed.y = *(unsigned int*)&hi;
        g_h0[i] = packed;
    }
    if (i < NUM_NODES) g_cnt[i] = 0;
}

// ---------------------------------------------------------------------------
// CSR build
// ---------------------------------------------------------------------------
__global__ void k_hist(const int* __restrict__ rows) {
    int e = blockIdx.x * blockDim.x + threadIdx.x;
    if (e < NUM_EDGES) atomicAdd(&g_cnt[rows[e]], 1);
}

__global__ void k_scan1() {
    __shared__ int sh[SCAN_T];
    int t = threadIdx.x;
    int i = blockIdx.x * SCAN_T + t;
    int v = (i < NUM_NODES) ? g_cnt[i] : 0;
    sh[t] = v;
    __syncthreads();
    #pragma unroll
    for (int off = 1; off < SCAN_T; off <<= 1) {
        int tmp = (t >= off) ? sh[t - off] : 0;
        __syncthreads();
        sh[t] += tmp;
        __syncthreads();
    }
    if (i < NUM_NODES) g_cursor[i] = sh[t];
    if (t == SCAN_T - 1) g_blocksums[blockIdx.x] = sh[t];
}

__global__ void k_scan2() {
    __shared__ int sh[256];
    int t = threadIdx.x;
    int v = (t < SCAN_NB) ? g_blocksums[t] : 0;
    sh[t] = v;
    __syncthreads();
    #pragma unroll
    for (int off = 1; off < 256; off <<= 1) {
        int tmp = (t >= off) ? sh[t - off] : 0;
        __syncthreads();
        sh[t] += tmp;
        __syncthreads();
    }
    if (t < SCAN_NB) g_blocksums[t] = sh[t] - v;   // exclusive
}

__global__ void k_scan3() {
    int i = blockIdx.x * blockDim.x + threadIdx.x;
    if (i < NUM_NODES) {
        int gi = g_cursor[i] + g_blocksums[i / SCAN_T];
        g_rowptr[i + 1] = gi;
        g_cursor[i] = gi - g_cnt[i];
        if (i == 0) g_rowptr[0] = 0;
    }
}

__global__ void k_scatter(const int* __restrict__ rows, const int* __restrict__ cols,
                          const float* __restrict__ vals) {
    int e = blockIdx.x * blockDim.x + threadIdx.x;
    if (e < NUM_EDGES) {
        int r = rows[e];
        int p = atomicAdd(&g_cursor[r], 1);
        g_csr[p] = make_int2(cols[e], __float_as_int(vals[e]));
    }
}

// ---------------------------------------------------------------------------
// CSR SpMM on fp16 features: warp per row, 4 halves (uint2) per lane,
// f32 register accumulation, single row store.
// FINAL=true: fuse out = 0.25 * (emb + h1 + h2 + acc), write f32 to d_out.
// ---------------------------------------------------------------------------
__device__ __forceinline__ void acc_edge(float4& acc, float v, uint2 raw) {
    __half2 lo = *(__half2*)&raw.x;
    __half2 hi = *(__half2*)&raw.y;
    float2 flo = __half22float2(lo);
    float2 fhi = __half22float2(hi);
    acc.x += v * flo.x;
    acc.y += v * flo.y;
    acc.z += v * fhi.x;
    acc.w += v * fhi.y;
}

template <bool FINAL>
__global__ void k_spmm(const uint2* __restrict__ x, uint2* __restrict__ y,
                       const float* __restrict__ emb, float* __restrict__ out) {
    int w    = (blockIdx.x * blockDim.x + threadIdx.x) >> 5;
    int lane = threadIdx.x & 31;
    if (w >= NUM_NODES) return;

    int s = __ldg(&g_rowptr[w]);
    int e = __ldg(&g_rowptr[w + 1]);

    float4 acc = make_float4(0.f, 0.f, 0.f, 0.f);

    int i = s;
    for (; i + 1 < e; i += 2) {
        int2 e0 = __ldg(&g_csr[i]);
        int2 e1 = __ldg(&g_csr[i + 1]);
        uint2 r0 = __ldg(x + (size_t)e0.x * 32 + lane);
        uint2 r1 = __ldg(x + (size_t)e1.x * 32 + lane);
        acc_edge(acc, __int_as_float(e0.y), r0);
        acc_edge(acc, __int_as_float(e1.y), r1);
    }
    if (i < e) {
        int2 e0 = __ldg(&g_csr[i]);
        uint2 r0 = __ldg(x + (size_t)e0.x * 32 + lane);
        acc_edge(acc, __int_as_float(e0.y), r0);
    }

    size_t idx = (size_t)w * 32 + lane;
    if (!FINAL) {
        __half2 lo = __floats2half2_rn(acc.x, acc.y);
        __half2 hi = __floats2half2_rn(acc.z, acc.w);
        uint2 packed;
        packed.x = *(unsigned int*)&lo;
        packed.y = *(unsigned int*)&hi;
        y[idx] = packed;
    } else {
        float4 m = ((const float4*)emb)[idx];
        uint2 a = __ldg(&g_h1[idx]);
        uint2 b = __ldg(&g_h2[idx]);
        float2 a_lo = __half22float2(*(__half2*)&a.x);
        float2 a_hi = __half22float2(*(__half2*)&a.y);
        float2 b_lo = __half22float2(*(__half2*)&b.x);
        float2 b_hi = __half22float2(*(__half2*)&b.y);
        float4 o;
        o.x = 0.25f * (m.x + a_lo.x + b_lo.x + acc.x);
        o.y = 0.25f * (m.y + a_lo.y + b_lo.y + acc.y);
        o.z = 0.25f * (m.z + a_hi.x + b_hi.x + acc.z);
        o.w = 0.25f * (m.w + a_hi.y + b_hi.y + acc.w);
        ((float4*)out)[idx] = o;
    }
}

extern "C" void kernel_launch(void* const* d_in, const int* in_sizes, int n_in,
                              void* d_out, int out_size) {
    const float* emb  = (const float*)d_in[0];
    const int*   rows = (const int*)  d_in[1];
    const int*   cols = (const int*)  d_in[2];
    const float* vals = (const float*)d_in[3];
    float*       out  = (float*)d_out;

    uint2 *h0 = nullptr, *h1 = nullptr, *h2 = nullptr;
    cudaGetSymbolAddress((void**)&h0, g_h0);
    cudaGetSymbolAddress((void**)&h1, g_h1);
    cudaGetSymbolAddress((void**)&h2, g_h2);

    const int TB = 256;
    const int node_blocks = (NUM_NODES + TB - 1) / TB;
    const int edge_blocks = (NUM_EDGES + TB - 1) / TB;
    const int elem_blocks = (TOTAL_VEC4 + TB - 1) / TB;
    const int spmm_blocks = (NUM_NODES * 32 + TB - 1) / TB;

    // convert emb->fp16 + zero counters (fused)
    k_convert_zero<<<elem_blocks, TB>>>(emb);

    // build CSR
    k_hist<<<edge_blocks, TB>>>(rows);
    k_scan1<<<SCAN_NB, SCAN_T>>>();
    k_scan2<<<1, 256>>>();
    k_scan3<<<node_blocks, TB>>>();
    k_scatter<<<edge_blocks, TB>>>(rows, cols, vals);

    // 3 propagation layers; layer 3 fuses the final average into d_out
    k_spmm<false><<<spmm_blocks, TB>>>(h0, h1, nullptr, nullptr);
    k_spmm<false><<<spmm_blocks, TB>>>(h1, h2, nullptr, nullptr);
    k_spmm<true ><<<spmm_blocks, TB>>>(h2, nullptr, emb, out);
}